// round 4
// baseline (speedup 1.0000x reference)
#include <cuda_runtime.h>
#include <math.h>

// ---------------- problem constants ----------------
#define BATCH   64
#define HH      56
#define WW2     56
#define CC      192
#define NHEADS  6
#define WSZ     7
#define SSHIFT  3
#define HIDDIM  768
#define NTOK    49           // tokens per window (7*7)
#define HDIM    32           // head dim
#define NWINS   4096         // 64 images * 64 windows
#define TTOT    200704       // B*H*W tokens
#define SCALEQ  0.17677669529663687f  // 32^-0.5

// ---------------- scratch (device globals: allocation-free rule) ----------------
__device__ float g_X  [(size_t)TTOT * CC];        // residual stream (token order)
__device__ float g_XW [(size_t)TTOT * CC];        // LN1-out (window order) / attn-out / LN2-out
__device__ float g_QKV[(size_t)TTOT * 3 * CC];    // qkv (window order)
__device__ float g_H1 [(size_t)TTOT * HIDDIM];    // MLP hidden

// =====================================================================
// LN1 + (shift) + window partition:  X[token] -> XW[window row]
// one warp per output window-row
// =====================================================================
__global__ __launch_bounds__(256) void ln_win_kernel(
    const float* __restrict__ src, float* __restrict__ dst,
    const float* __restrict__ g, const float* __restrict__ bta, int shifted)
{
    int warp = threadIdx.x >> 5, lane = threadIdx.x & 31;
    int m = blockIdx.x * 8 + warp;                 // window-layout row
    int win = m / NTOK, n = m - win * NTOK;
    int b = win >> 6, wl = win & 63;
    int hs = (wl >> 3) * WSZ + n / WSZ;
    int ws = (wl & 7)  * WSZ + n % WSZ;
    if (shifted) { hs = (hs + SSHIFT) % HH; ws = (ws + SSHIFT) % WW2; }
    size_t t = ((size_t)b * HH + hs) * WW2 + ws;
    const float* xp = src + t * CC;
    float v[6]; float s = 0.f, ss = 0.f;
    #pragma unroll
    for (int j = 0; j < 6; j++) { v[j] = xp[lane + 32*j]; s += v[j]; ss += v[j]*v[j]; }
    #pragma unroll
    for (int o = 16; o > 0; o >>= 1) {
        s  += __shfl_xor_sync(0xffffffffu, s,  o);
        ss += __shfl_xor_sync(0xffffffffu, ss, o);
    }
    float mu   = s * (1.f / CC);
    float rstd = rsqrtf(ss * (1.f / CC) - mu * mu + 1e-5f);
    float* op = dst + (size_t)m * CC;
    #pragma unroll
    for (int j = 0; j < 6; j++) {
        int c = lane + 32*j;
        op[c] = (v[j] - mu) * rstd * g[c] + bta[c];
    }
}

// LN2 in token order (identity mapping)
__global__ __launch_bounds__(256) void ln_tok_kernel(
    const float* __restrict__ src, float* __restrict__ dst,
    const float* __restrict__ g, const float* __restrict__ bta)
{
    int warp = threadIdx.x >> 5, lane = threadIdx.x & 31;
    int m = blockIdx.x * 8 + warp;
    const float* xp = src + (size_t)m * CC;
    float v[6]; float s = 0.f, ss = 0.f;
    #pragma unroll
    for (int j = 0; j < 6; j++) { v[j] = xp[lane + 32*j]; s += v[j]; ss += v[j]*v[j]; }
    #pragma unroll
    for (int o = 16; o > 0; o >>= 1) {
        s  += __shfl_xor_sync(0xffffffffu, s,  o);
        ss += __shfl_xor_sync(0xffffffffu, ss, o);
    }
    float mu   = s * (1.f / CC);
    float rstd = rsqrtf(ss * (1.f / CC) - mu * mu + 1e-5f);
    float* op = dst + (size_t)m * CC;
    #pragma unroll
    for (int j = 0; j < 6; j++) {
        int c = lane + 32*j;
        op[c] = (v[j] - mu) * rstd * g[c] + bta[c];
    }
}

// =====================================================================
// Window attention: one block per (window, head).
// scores = (q*scale)@k^T + rel-pos-bias (+ shift mask), softmax, @v
// =====================================================================
__global__ __launch_bounds__(128) void attn_kernel(
    const float* __restrict__ qkv, float* __restrict__ outp,
    const float* __restrict__ rpb, int shifted)
{
    int win = blockIdx.x / NHEADS;
    int hd  = blockIdx.x % NHEADS;
    __shared__ float q[NTOK][HDIM + 1];
    __shared__ float k[NTOK][HDIM + 1];
    __shared__ float v[NTOK][HDIM + 1];
    __shared__ float sc[NTOK][52];
    __shared__ int   lab[NTOK];
    int tid = threadIdx.x;

    const float* base = qkv + (size_t)win * NTOK * 576 + hd * HDIM;
    for (int idx = tid; idx < NTOK * HDIM; idx += 128) {
        int i = idx >> 5, d = idx & 31;
        const float* row = base + (size_t)i * 576 + d;
        q[i][d] = row[0]   * SCALEQ;
        k[i][d] = row[192];
        v[i][d] = row[384];
    }
    if (shifted && tid < NTOK) {
        int wl = win & 63;
        int h = (wl >> 3) * WSZ + tid / WSZ;   // shifted-frame coords
        int w = (wl & 7)  * WSZ + tid % WSZ;
        int rc = (h < HH  - WSZ) ? 0 : ((h < HH  - SSHIFT) ? 1 : 2);
        int cc = (w < WW2 - WSZ) ? 0 : ((w < WW2 - SSHIFT) ? 1 : 2);
        lab[tid] = rc * 3 + cc;
    }
    __syncthreads();

    for (int idx = tid; idx < NTOK * NTOK; idx += 128) {
        int i = idx / NTOK, j = idx - i * NTOK;
        float acc = 0.f;
        #pragma unroll
        for (int d = 0; d < HDIM; d++) acc += q[i][d] * k[j][d];
        int ridx = (i / WSZ - j / WSZ + WSZ - 1) * (2 * WSZ - 1)
                 + (i % WSZ - j % WSZ + WSZ - 1);
        acc += rpb[ridx * NHEADS + hd];
        if (shifted && lab[i] != lab[j]) acc -= 100.f;
        sc[i][j] = acc;
    }
    __syncthreads();

    int warp = tid >> 5, lane = tid & 31;
    for (int i = warp; i < NTOK; i += 4) {
        float a0 = (lane < NTOK)      ? sc[i][lane]      : -1e30f;
        float a1 = (lane + 32 < NTOK) ? sc[i][lane + 32] : -1e30f;
        float mx = fmaxf(a0, a1);
        #pragma unroll
        for (int o = 16; o > 0; o >>= 1) mx = fmaxf(mx, __shfl_xor_sync(0xffffffffu, mx, o));
        float e0 = (lane < NTOK)      ? __expf(a0 - mx) : 0.f;
        float e1 = (lane + 32 < NTOK) ? __expf(a1 - mx) : 0.f;
        float sum = e0 + e1;
        #pragma unroll
        for (int o = 16; o > 0; o >>= 1) sum += __shfl_xor_sync(0xffffffffu, sum, o);
        float inv = 1.f / sum;
        if (lane < NTOK)      sc[i][lane]      = e0 * inv;
        if (lane + 32 < NTOK) sc[i][lane + 32] = e1 * inv;
    }
    __syncthreads();

    float* obase = outp + (size_t)win * NTOK * CC + hd * HDIM;
    for (int idx = tid; idx < NTOK * HDIM; idx += 128) {
        int i = idx >> 5, d = idx & 31;
        float acc = 0.f;
        #pragma unroll
        for (int j = 0; j < NTOK; j++) acc += sc[i][j] * v[j][d];
        obase[(size_t)i * CC + d] = acc;
    }
}

// =====================================================================
// Generic fp32 SGEMM: C = A[M,K] @ W[K,N] + bias, M=200704 (mult of 128),
// N in {192,576,768} (mult of 64), K in {192,768} (mult of 16).
// BM=128 BN=64 BK=16, 256 threads, 8x4 register tile, reg prefetch.
// EPI: 0 = store (qkv); 1 = window-reverse(+unshift) residual scatter (proj);
//      2 = exact GELU store (fc1); 3 = residual add token-order (fc2)
// =====================================================================
template<int EPI>
__global__ __launch_bounds__(256) void gemm_kernel(
    const float* __restrict__ A, const float* __restrict__ Wt,
    const float* __restrict__ bias, float* __restrict__ Cout,
    int N, int K, int shifted)
{
    __shared__ float As[16][128];
    __shared__ float Bs[16][64];
    int tid = threadIdx.x;
    int m0 = blockIdx.y * 128, n0 = blockIdx.x * 64;

    int arow0 = tid >> 2, arow1 = arow0 + 64;
    int ak    = (tid & 3) * 4;
    int brow  = tid >> 4,  bcol  = (tid & 15) * 4;

    const float* Ag0 = A  + (size_t)(m0 + arow0) * K + ak;
    const float* Ag1 = A  + (size_t)(m0 + arow1) * K + ak;
    const float* Bg  = Wt + (size_t)brow * N + n0 + bcol;

    float4 pa0 = *(const float4*)Ag0;
    float4 pa1 = *(const float4*)Ag1;
    float4 pb  = *(const float4*)Bg;

    float acc[8][4];
    #pragma unroll
    for (int i = 0; i < 8; i++)
        #pragma unroll
        for (int j = 0; j < 4; j++) acc[i][j] = 0.f;

    int tx = tid & 15, ty = tid >> 4;
    int ktiles = K >> 4;
    for (int kt = 0; kt < ktiles; kt++) {
        As[ak  ][arow0] = pa0.x; As[ak+1][arow0] = pa0.y;
        As[ak+2][arow0] = pa0.z; As[ak+3][arow0] = pa0.w;
        As[ak  ][arow1] = pa1.x; As[ak+1][arow1] = pa1.y;
        As[ak+2][arow1] = pa1.z; As[ak+3][arow1] = pa1.w;
        *(float4*)&Bs[brow][bcol] = pb;
        __syncthreads();
        if (kt + 1 < ktiles) {
            pa0 = *(const float4*)(Ag0 + (kt + 1) * 16);
            pa1 = *(const float4*)(Ag1 + (kt + 1) * 16);
            pb  = *(const float4*)(Bg  + (size_t)(kt + 1) * 16 * N);
        }
        #pragma unroll
        for (int kk = 0; kk < 16; kk++) {
            float a[8], b4[4];
            *(float4*)&a[0] = *(const float4*)&As[kk][ty * 8];
            *(float4*)&a[4] = *(const float4*)&As[kk][ty * 8 + 4];
            *(float4*)&b4[0] = *(const float4*)&Bs[kk][tx * 4];
            #pragma unroll
            for (int i = 0; i < 8; i++)
                #pragma unroll
                for (int j = 0; j < 4; j++)
                    acc[i][j] = fmaf(a[i], b4[j], acc[i][j]);
        }
        __syncthreads();
    }

    #pragma unroll
    for (int i = 0; i < 8; i++) {
        int m = m0 + ty * 8 + i;
        size_t orow;
        if (EPI == 1) {
            int win = m / NTOK, n = m - win * NTOK;
            int b = win >> 6, wl = win & 63;
            int hs = (wl >> 3) * WSZ + n / WSZ;
            int ws = (wl & 7)  * WSZ + n % WSZ;
            if (shifted) { hs = (hs + SSHIFT) % HH; ws = (ws + SSHIFT) % WW2; }
            orow = (((size_t)b * HH + hs) * WW2 + ws) * CC;
        } else if (EPI == 3) {
            orow = (size_t)m * CC;
        } else {
            orow = (size_t)m * N;
        }
        #pragma unroll
        for (int j = 0; j < 4; j++) {
            int n = n0 + tx * 4 + j;
            float val = acc[i][j] + bias[n];
            if (EPI == 0)       Cout[orow + n] = val;
            else if (EPI == 2)  Cout[orow + n] = 0.5f * val * (1.f + erff(val * 0.70710678118654752f));
            else                Cout[orow + n] += val;   // EPI 1 & 3: residual add
        }
    }
}

// =====================================================================
extern "C" void kernel_launch(void* const* d_in, const int* in_sizes, int n_in,
                              void* d_out, int out_size)
{
    (void)in_sizes; (void)n_in; (void)out_size;
    const float* x     = (const float*)d_in[0];
    const float* ln1g  = (const float*)d_in[1];
    const float* ln1b  = (const float*)d_in[2];
    const float* qkvw  = (const float*)d_in[3];
    const float* qkvb  = (const float*)d_in[4];
    const float* rpb   = (const float*)d_in[5];
    const float* projw = (const float*)d_in[6];
    const float* projb = (const float*)d_in[7];
    const float* ln2g  = (const float*)d_in[8];
    const float* ln2b  = (const float*)d_in[9];
    const float* fc1w  = (const float*)d_in[10];
    const float* fc1b  = (const float*)d_in[11];
    const float* fc2w  = (const float*)d_in[12];
    const float* fc2b  = (const float*)d_in[13];

    float *X, *XW, *QKV, *H1;
    cudaGetSymbolAddress((void**)&X,   g_X);
    cudaGetSymbolAddress((void**)&XW,  g_XW);
    cudaGetSymbolAddress((void**)&QKV, g_QKV);
    cudaGetSymbolAddress((void**)&H1,  g_H1);

    size_t xbytes = (size_t)TTOT * CC * sizeof(float);
    cudaMemcpyAsync(X, x, xbytes, cudaMemcpyDeviceToDevice);

    for (int layer = 0; layer < 2; layer++) {
        int shifted = layer & 1;
        // LN1 + shift + window partition
        ln_win_kernel<<<TTOT / 8, 256>>>(X, XW, ln1g + layer * CC, ln1b + layer * CC, shifted);
        // QKV GEMM
        gemm_kernel<0><<<dim3(576 / 64, TTOT / 128), 256>>>(
            XW, qkvw + (size_t)layer * CC * 576, qkvb + layer * 576, QKV, 576, CC, 0);
        // attention (writes attn-out into XW)
        attn_kernel<<<NWINS * NHEADS, 128>>>(QKV, XW, rpb + layer * 169 * NHEADS, shifted);
        // proj GEMM + window-reverse + unshift + residual into X
        gemm_kernel<1><<<dim3(192 / 64, TTOT / 128), 256>>>(
            XW, projw + (size_t)layer * CC * CC, projb + layer * CC, X, CC, CC, shifted);
        // LN2
        ln_tok_kernel<<<TTOT / 8, 256>>>(X, XW, ln2g + layer * CC, ln2b + layer * CC);
        // fc1 + exact GELU
        gemm_kernel<2><<<dim3(768 / 64, TTOT / 128), 256>>>(
            XW, fc1w + (size_t)layer * CC * HIDDIM, fc1b + layer * HIDDIM, H1, HIDDIM, CC, 0);
        // fc2 + residual into X
        gemm_kernel<3><<<dim3(192 / 64, TTOT / 128), 256>>>(
            H1, fc2w + (size_t)layer * HIDDIM * CC, fc2b + layer * CC, X, CC, HIDDIM, 0);
    }

    cudaMemcpyAsync(d_out, X, xbytes, cudaMemcpyDeviceToDevice);
}

// round 6
// speedup vs baseline: 1.4370x; 1.4370x over previous
#include <cuda_runtime.h>
#include <cuda_bf16.h>
#include <math.h>
#include <cstdint>

// ---------------- problem constants ----------------
#define HH      56
#define WW2     56
#define CC      192
#define NHEADS  6
#define WSZ     7
#define SSHIFT  3
#define HIDDIM  768
#define NTOK    49
#define HDIM    32
#define NWINS   4096
#define TTOT    200704
#define SCALEQ  0.17677669529663687f

// ---------------- scratch ----------------
__device__ float g_X  [(size_t)TTOT * CC];
__device__ float g_XW [(size_t)TTOT * CC];
__device__ float g_QKV[(size_t)TTOT * 3 * CC];
__device__ float g_H1 [(size_t)TTOT * HIDDIM];

// split weights, transposed to [N][K] bf16 (hi + lo)
__device__ __nv_bfloat16 g_Wqkv_h[2 * 576 * 192];
__device__ __nv_bfloat16 g_Wqkv_l[2 * 576 * 192];
__device__ __nv_bfloat16 g_Wprj_h[2 * 192 * 192];
__device__ __nv_bfloat16 g_Wprj_l[2 * 192 * 192];
__device__ __nv_bfloat16 g_Wfc1_h[2 * 768 * 192];
__device__ __nv_bfloat16 g_Wfc1_l[2 * 768 * 192];
__device__ __nv_bfloat16 g_Wfc2_h[2 * 192 * 768];
__device__ __nv_bfloat16 g_Wfc2_l[2 * 192 * 768];

// ====================== weight transpose + split ======================
__global__ __launch_bounds__(256) void wsplit_kernel(
    const float* __restrict__ W, __nv_bfloat16* __restrict__ hi,
    __nv_bfloat16* __restrict__ lo, int K, int N)
{
    int idx = blockIdx.x * 256 + threadIdx.x;
    if (idx >= K * N) return;
    int k = idx / N, n = idx - k * N;
    float v = W[idx];
    __nv_bfloat16 h = __float2bfloat16_rn(v);
    __nv_bfloat16 l = __float2bfloat16_rn(v - __bfloat162float(h));
    hi[(size_t)n * K + k] = h;
    lo[(size_t)n * K + k] = l;
}

// ====================== LN kernels ======================
__global__ __launch_bounds__(256) void ln_win_kernel(
    const float* __restrict__ src, float* __restrict__ dst,
    const float* __restrict__ g, const float* __restrict__ bta, int shifted)
{
    int warp = threadIdx.x >> 5, lane = threadIdx.x & 31;
    int m = blockIdx.x * 8 + warp;
    int win = m / NTOK, n = m - win * NTOK;
    int b = win >> 6, wl = win & 63;
    int hs = (wl >> 3) * WSZ + n / WSZ;
    int ws = (wl & 7)  * WSZ + n % WSZ;
    if (shifted) { hs = (hs + SSHIFT) % HH; ws = (ws + SSHIFT) % WW2; }
    size_t t = ((size_t)b * HH + hs) * WW2 + ws;
    const float* xp = src + t * CC;
    float v[6]; float s = 0.f, ss = 0.f;
    #pragma unroll
    for (int j = 0; j < 6; j++) { v[j] = xp[lane + 32*j]; s += v[j]; ss += v[j]*v[j]; }
    #pragma unroll
    for (int o = 16; o > 0; o >>= 1) {
        s  += __shfl_xor_sync(0xffffffffu, s,  o);
        ss += __shfl_xor_sync(0xffffffffu, ss, o);
    }
    float mu = s * (1.f / CC);
    float rstd = rsqrtf(ss * (1.f / CC) - mu * mu + 1e-5f);
    float* op = dst + (size_t)m * CC;
    #pragma unroll
    for (int j = 0; j < 6; j++) {
        int c = lane + 32*j;
        op[c] = (v[j] - mu) * rstd * g[c] + bta[c];
    }
}

__global__ __launch_bounds__(256) void ln_tok_kernel(
    const float* __restrict__ src, float* __restrict__ dst,
    const float* __restrict__ g, const float* __restrict__ bta)
{
    int warp = threadIdx.x >> 5, lane = threadIdx.x & 31;
    int m = blockIdx.x * 8 + warp;
    const float* xp = src + (size_t)m * CC;
    float v[6]; float s = 0.f, ss = 0.f;
    #pragma unroll
    for (int j = 0; j < 6; j++) { v[j] = xp[lane + 32*j]; s += v[j]; ss += v[j]*v[j]; }
    #pragma unroll
    for (int o = 16; o > 0; o >>= 1) {
        s  += __shfl_xor_sync(0xffffffffu, s,  o);
        ss += __shfl_xor_sync(0xffffffffu, ss, o);
    }
    float mu = s * (1.f / CC);
    float rstd = rsqrtf(ss * (1.f / CC) - mu * mu + 1e-5f);
    float* op = dst + (size_t)m * CC;
    #pragma unroll
    for (int j = 0; j < 6; j++) {
        int c = lane + 32*j;
        op[c] = (v[j] - mu) * rstd * g[c] + bta[c];
    }
}

// ====================== window attention ======================
__global__ __launch_bounds__(128) void attn_kernel(
    const float* __restrict__ qkv, float* __restrict__ outp,
    const float* __restrict__ rpb, int shifted)
{
    int win = blockIdx.x / NHEADS;
    int hd  = blockIdx.x % NHEADS;
    __shared__ float q[NTOK][HDIM + 1];
    __shared__ float k[NTOK][HDIM + 1];
    __shared__ float v[NTOK][HDIM + 1];
    __shared__ float sc[NTOK][52];
    __shared__ int   lab[NTOK];
    int tid = threadIdx.x;

    const float* base = qkv + (size_t)win * NTOK * 576 + hd * HDIM;
    for (int idx = tid; idx < NTOK * HDIM; idx += 128) {
        int i = idx >> 5, d = idx & 31;
        const float* row = base + (size_t)i * 576 + d;
        q[i][d] = row[0]   * SCALEQ;
        k[i][d] = row[192];
        v[i][d] = row[384];
    }
    if (shifted && tid < NTOK) {
        int wl = win & 63;
        int h = (wl >> 3) * WSZ + tid / WSZ;
        int w = (wl & 7)  * WSZ + tid % WSZ;
        int rc = (h < HH  - WSZ) ? 0 : ((h < HH  - SSHIFT) ? 1 : 2);
        int cc = (w < WW2 - WSZ) ? 0 : ((w < WW2 - SSHIFT) ? 1 : 2);
        lab[tid] = rc * 3 + cc;
    }
    __syncthreads();

    for (int idx = tid; idx < NTOK * NTOK; idx += 128) {
        int i = idx / NTOK, j = idx - i * NTOK;
        float acc = 0.f;
        #pragma unroll
        for (int d = 0; d < HDIM; d++) acc += q[i][d] * k[j][d];
        int ridx = (i / WSZ - j / WSZ + WSZ - 1) * (2 * WSZ - 1)
                 + (i % WSZ - j % WSZ + WSZ - 1);
        acc += rpb[ridx * NHEADS + hd];
        if (shifted && lab[i] != lab[j]) acc -= 100.f;
        sc[i][j] = acc;
    }
    __syncthreads();

    int warp = tid >> 5, lane = tid & 31;
    for (int i = warp; i < NTOK; i += 4) {
        float a0 = (lane < NTOK)      ? sc[i][lane]      : -1e30f;
        float a1 = (lane + 32 < NTOK) ? sc[i][lane + 32] : -1e30f;
        float mx = fmaxf(a0, a1);
        #pragma unroll
        for (int o = 16; o > 0; o >>= 1) mx = fmaxf(mx, __shfl_xor_sync(0xffffffffu, mx, o));
        float e0 = (lane < NTOK)      ? __expf(a0 - mx) : 0.f;
        float e1 = (lane + 32 < NTOK) ? __expf(a1 - mx) : 0.f;
        float sum = e0 + e1;
        #pragma unroll
        for (int o = 16; o > 0; o >>= 1) sum += __shfl_xor_sync(0xffffffffu, sum, o);
        float inv = 1.f / sum;
        if (lane < NTOK)      sc[i][lane]      = e0 * inv;
        if (lane + 32 < NTOK) sc[i][lane + 32] = e1 * inv;
    }
    __syncthreads();

    float* obase = outp + (size_t)win * NTOK * CC + hd * HDIM;
    for (int idx = tid; idx < NTOK * HDIM; idx += 128) {
        int i = idx >> 5, d = idx & 31;
        float acc = 0.f;
        #pragma unroll
        for (int j = 0; j < NTOK; j++) acc += sc[i][j] * v[j][d];
        obase[(size_t)i * CC + d] = acc;
    }
}

// ====================== bf16 hi/lo tensor-core GEMM (mma.sync) ======================
// C[M,N] = A[M,K](fp32) @ W[K,N] + bias. W pre-split to bf16 hi/lo, [N][K].
// BM=128, BN=64, BK=32, 256 threads (8 warps, 4x2 warp grid, warp tile 32x32).
// 3 passes: Ah*Bh + Ah*Bl + Al*Bh.
// EPI: 0 store; 1 win-reverse(+unshift) residual; 2 exact GELU; 3 residual.
#define BK      32
#define BN      64
#define STRD    40                 // smem row stride in bf16 (80B -> conflict-free frag loads)
#define A_SZ    (128 * STRD)       // 5120
#define B_SZ    (BN * STRD)        // 2560
#define OFF_AHI 0
#define OFF_ALO A_SZ
#define OFF_BHI (2 * A_SZ)
#define OFF_BLO (2 * A_SZ + B_SZ)
#define STAGE   (2 * A_SZ + 2 * B_SZ)        // 15360 bf16 = 30720 B
#define GSMEM   (2 * STAGE * 2)              // bytes: 61440

__device__ __forceinline__ void split8(float4 v0, float4 v1, uint4& hi, uint4& lo)
{
    float f[8] = {v0.x, v0.y, v0.z, v0.w, v1.x, v1.y, v1.z, v1.w};
    uint32_t hb[8], lb[8];
    #pragma unroll
    for (int i = 0; i < 8; i++) {
        __nv_bfloat16 h = __float2bfloat16_rn(f[i]);
        __nv_bfloat16 l = __float2bfloat16_rn(f[i] - __bfloat162float(h));
        hb[i] = (uint32_t)__bfloat16_as_ushort(h);
        lb[i] = (uint32_t)__bfloat16_as_ushort(l);
    }
    hi.x = hb[0] | (hb[1] << 16); hi.y = hb[2] | (hb[3] << 16);
    hi.z = hb[4] | (hb[5] << 16); hi.w = hb[6] | (hb[7] << 16);
    lo.x = lb[0] | (lb[1] << 16); lo.y = lb[2] | (lb[3] << 16);
    lo.z = lb[4] | (lb[5] << 16); lo.w = lb[6] | (lb[7] << 16);
}

__device__ __forceinline__ void mma16816(float* c, const uint32_t* a, const uint32_t* b)
{
    asm volatile(
        "mma.sync.aligned.m16n8k16.row.col.f32.bf16.bf16.f32 "
        "{%0,%1,%2,%3}, {%4,%5,%6,%7}, {%8,%9}, {%0,%1,%2,%3};"
        : "+f"(c[0]), "+f"(c[1]), "+f"(c[2]), "+f"(c[3])
        : "r"(a[0]), "r"(a[1]), "r"(a[2]), "r"(a[3]), "r"(b[0]), "r"(b[1]));
}

template<int EPI>
__global__ __launch_bounds__(256, 2) void mma_gemm_kernel(
    const float* __restrict__ A,
    const __nv_bfloat16* __restrict__ Bhi, const __nv_bfloat16* __restrict__ Blo,
    const float* __restrict__ bias, float* __restrict__ Cout,
    int N, int K, int shifted)
{
    extern __shared__ __nv_bfloat16 sm[];
    int tid = threadIdx.x;
    int wid = tid >> 5, lane = tid & 31;
    int wr = wid >> 1, wc = wid & 1;        // warp tile: rows wr*32, cols wc*32
    int g = lane >> 2, t2 = (lane & 3) * 2; // mma fragment coords
    int m0 = blockIdx.y * 128, n0 = blockIdx.x * BN;

    // global prefetch assignments
    int ar = tid >> 1, ahf = tid & 1;       // A: 2 threads per row, 16 floats each
    int br = tid >> 2, bc = tid & 3;        // B: 4 threads per row, 8 bf16 each
    const float*         Ap  = A   + (size_t)(m0 + ar) * K + ahf * 16;
    const __nv_bfloat16* Bph = Bhi + (size_t)(n0 + br) * K + bc * 8;
    const __nv_bfloat16* Bpl = Blo + (size_t)(n0 + br) * K + bc * 8;

    float acc[2][4][4];
    #pragma unroll
    for (int mt = 0; mt < 2; mt++)
        #pragma unroll
        for (int nt = 0; nt < 4; nt++)
            #pragma unroll
            for (int r = 0; r < 4; r++) acc[mt][nt][r] = 0.f;

    float4 pa[4]; uint4 pbh, pbl;
    pa[0] = *(const float4*)(Ap + 0);  pa[1] = *(const float4*)(Ap + 4);
    pa[2] = *(const float4*)(Ap + 8);  pa[3] = *(const float4*)(Ap + 12);
    pbh = *(const uint4*)Bph; pbl = *(const uint4*)Bpl;

    int KT = K >> 5;
    for (int kt = 0; kt < KT; kt++) {
        __nv_bfloat16* st = sm + (kt & 1) * STAGE;
        // ---- STS with hi/lo split ----
        {
            uint4 h0, l0, h1, l1;
            split8(pa[0], pa[1], h0, l0);
            split8(pa[2], pa[3], h1, l1);
            uint4* dh = (uint4*)&st[OFF_AHI + ar * STRD + ahf * 16];
            uint4* dl = (uint4*)&st[OFF_ALO + ar * STRD + ahf * 16];
            dh[0] = h0; dh[1] = h1;
            dl[0] = l0; dl[1] = l1;
            *(uint4*)&st[OFF_BHI + br * STRD + bc * 8] = pbh;
            *(uint4*)&st[OFF_BLO + br * STRD + bc * 8] = pbl;
        }
        __syncthreads();
        if (kt + 1 < KT) {
            const float* ap2 = Ap + (kt + 1) * 32;
            pa[0] = *(const float4*)(ap2 + 0);  pa[1] = *(const float4*)(ap2 + 4);
            pa[2] = *(const float4*)(ap2 + 8);  pa[3] = *(const float4*)(ap2 + 12);
            pbh = *(const uint4*)(Bph + (kt + 1) * 32);
            pbl = *(const uint4*)(Bpl + (kt + 1) * 32);
        }
        // ---- compute from this buffer ----
        const __nv_bfloat16* cs = sm + (kt & 1) * STAGE;
        #pragma unroll
        for (int kk = 0; kk < 32; kk += 16) {
            uint32_t afh[2][4], afl[2][4], bfh[4][2], bfl[4][2];
            #pragma unroll
            for (int mt = 0; mt < 2; mt++) {
                int r0 = (wr * 32 + mt * 16 + g) * STRD + kk + t2;
                afh[mt][0] = *(const uint32_t*)&cs[OFF_AHI + r0];
                afh[mt][1] = *(const uint32_t*)&cs[OFF_AHI + r0 + 8 * STRD];
                afh[mt][2] = *(const uint32_t*)&cs[OFF_AHI + r0 + 8];
                afh[mt][3] = *(const uint32_t*)&cs[OFF_AHI + r0 + 8 * STRD + 8];
            }
            #pragma unroll
            for (int nt = 0; nt < 4; nt++) {
                int rb = (wc * 32 + nt * 8 + g) * STRD + kk + t2;
                bfh[nt][0] = *(const uint32_t*)&cs[OFF_BHI + rb];
                bfh[nt][1] = *(const uint32_t*)&cs[OFF_BHI + rb + 8];
            }
            #pragma unroll
            for (int mt = 0; mt < 2; mt++)
                #pragma unroll
                for (int nt = 0; nt < 4; nt++)
                    mma16816(acc[mt][nt], afh[mt], bfh[nt]);
            #pragma unroll
            for (int nt = 0; nt < 4; nt++) {
                int rb = (wc * 32 + nt * 8 + g) * STRD + kk + t2;
                bfl[nt][0] = *(const uint32_t*)&cs[OFF_BLO + rb];
                bfl[nt][1] = *(const uint32_t*)&cs[OFF_BLO + rb + 8];
            }
            #pragma unroll
            for (int mt = 0; mt < 2; mt++)
                #pragma unroll
                for (int nt = 0; nt < 4; nt++)
                    mma16816(acc[mt][nt], afh[mt], bfl[nt]);
            #pragma unroll
            for (int mt = 0; mt < 2; mt++) {
                int r0 = (wr * 32 + mt * 16 + g) * STRD + kk + t2;
                afl[mt][0] = *(const uint32_t*)&cs[OFF_ALO + r0];
                afl[mt][1] = *(const uint32_t*)&cs[OFF_ALO + r0 + 8 * STRD];
                afl[mt][2] = *(const uint32_t*)&cs[OFF_ALO + r0 + 8];
                afl[mt][3] = *(const uint32_t*)&cs[OFF_ALO + r0 + 8 * STRD + 8];
            }
            #pragma unroll
            for (int mt = 0; mt < 2; mt++)
                #pragma unroll
                for (int nt = 0; nt < 4; nt++)
                    mma16816(acc[mt][nt], afl[mt], bfh[nt]);
        }
        __syncthreads();
    }

    // ---- epilogue ----
    #pragma unroll
    for (int mt = 0; mt < 2; mt++) {
        #pragma unroll
        for (int hf = 0; hf < 2; hf++) {
            int m = m0 + wr * 32 + mt * 16 + hf * 8 + g;
            size_t orow;
            if (EPI == 1) {
                int win = m / NTOK, n = m - win * NTOK;
                int b = win >> 6, wl = win & 63;
                int hs = (wl >> 3) * WSZ + n / WSZ;
                int ws = (wl & 7)  * WSZ + n % WSZ;
                if (shifted) { hs = (hs + SSHIFT) % HH; ws = (ws + SSHIFT) % WW2; }
                orow = (((size_t)b * HH + hs) * WW2 + ws) * CC;
            } else if (EPI == 3) {
                orow = (size_t)m * CC;
            } else {
                orow = (size_t)m * N;
            }
            #pragma unroll
            for (int nt = 0; nt < 4; nt++) {
                int n = n0 + wc * 32 + nt * 8 + t2;
                float vx = acc[mt][nt][hf * 2 + 0] + bias[n];
                float vy = acc[mt][nt][hf * 2 + 1] + bias[n + 1];
                if (EPI == 2) {
                    vx = 0.5f * vx * (1.f + erff(vx * 0.70710678118654752f));
                    vy = 0.5f * vy * (1.f + erff(vy * 0.70710678118654752f));
                }
                float* op = &Cout[orow + n];
                if (EPI == 0 || EPI == 2) {
                    float2 v = {vx, vy};
                    *(float2*)op = v;
                } else {
                    float2 o = *(const float2*)op;
                    o.x += vx; o.y += vy;
                    *(float2*)op = o;
                }
            }
        }
    }
}

// ====================== launch ======================
extern "C" void kernel_launch(void* const* d_in, const int* in_sizes, int n_in,
                              void* d_out, int out_size)
{
    (void)in_sizes; (void)n_in; (void)out_size;
    const float* x     = (const float*)d_in[0];
    const float* ln1g  = (const float*)d_in[1];
    const float* ln1b  = (const float*)d_in[2];
    const float* qkvw  = (const float*)d_in[3];
    const float* qkvb  = (const float*)d_in[4];
    const float* rpb   = (const float*)d_in[5];
    const float* projw = (const float*)d_in[6];
    const float* projb = (const float*)d_in[7];
    const float* ln2g  = (const float*)d_in[8];
    const float* ln2b  = (const float*)d_in[9];
    const float* fc1w  = (const float*)d_in[10];
    const float* fc1b  = (const float*)d_in[11];
    const float* fc2w  = (const float*)d_in[12];
    const float* fc2b  = (const float*)d_in[13];

    float *X, *XW, *QKV, *H1;
    cudaGetSymbolAddress((void**)&X,   g_X);
    cudaGetSymbolAddress((void**)&XW,  g_XW);
    cudaGetSymbolAddress((void**)&QKV, g_QKV);
    cudaGetSymbolAddress((void**)&H1,  g_H1);

    __nv_bfloat16 *Wqh, *Wql, *Wph, *Wpl, *W1h, *W1l, *W2h, *W2l;
    cudaGetSymbolAddress((void**)&Wqh, g_Wqkv_h); cudaGetSymbolAddress((void**)&Wql, g_Wqkv_l);
    cudaGetSymbolAddress((void**)&Wph, g_Wprj_h); cudaGetSymbolAddress((void**)&Wpl, g_Wprj_l);
    cudaGetSymbolAddress((void**)&W1h, g_Wfc1_h); cudaGetSymbolAddress((void**)&W1l, g_Wfc1_l);
    cudaGetSymbolAddress((void**)&W2h, g_Wfc2_h); cudaGetSymbolAddress((void**)&W2l, g_Wfc2_l);

    cudaFuncSetAttribute(mma_gemm_kernel<0>, cudaFuncAttributeMaxDynamicSharedMemorySize, GSMEM);
    cudaFuncSetAttribute(mma_gemm_kernel<1>, cudaFuncAttributeMaxDynamicSharedMemorySize, GSMEM);
    cudaFuncSetAttribute(mma_gemm_kernel<2>, cudaFuncAttributeMaxDynamicSharedMemorySize, GSMEM);
    cudaFuncSetAttribute(mma_gemm_kernel<3>, cudaFuncAttributeMaxDynamicSharedMemorySize, GSMEM);

    // weight transpose + hi/lo split (both layers)
    for (int layer = 0; layer < 2; layer++) {
        size_t oq = (size_t)layer * 192 * 576;
        size_t op = (size_t)layer * 192 * 192;
        size_t o1 = (size_t)layer * 192 * 768;
        size_t o2 = (size_t)layer * 768 * 192;
        wsplit_kernel<<<(192*576 + 255)/256, 256>>>(qkvw + oq, Wqh + oq, Wql + oq, 192, 576);
        wsplit_kernel<<<(192*192 + 255)/256, 256>>>(projw + op, Wph + op, Wpl + op, 192, 192);
        wsplit_kernel<<<(192*768 + 255)/256, 256>>>(fc1w + o1, W1h + o1, W1l + o1, 192, 768);
        wsplit_kernel<<<(768*192 + 255)/256, 256>>>(fc2w + o2, W2h + o2, W2l + o2, 768, 192);
    }

    size_t xbytes = (size_t)TTOT * CC * sizeof(float);
    cudaMemcpyAsync(X, x, xbytes, cudaMemcpyDeviceToDevice);

    const int MB = TTOT / 128;  // 1568
    for (int layer = 0; layer < 2; layer++) {
        int shifted = layer & 1;
        size_t oq = (size_t)layer * 192 * 576;
        size_t op = (size_t)layer * 192 * 192;
        size_t o1 = (size_t)layer * 192 * 768;
        size_t o2 = (size_t)layer * 768 * 192;

        ln_win_kernel<<<TTOT / 8, 256>>>(X, XW, ln1g + layer * CC, ln1b + layer * CC, shifted);
        mma_gemm_kernel<0><<<dim3(576 / BN, MB), 256, GSMEM>>>(
            XW, Wqh + oq, Wql + oq, qkvb + layer * 576, QKV, 576, 192, 0);
        attn_kernel<<<NWINS * NHEADS, 128>>>(QKV, XW, rpb + layer * 169 * NHEADS, shifted);
        mma_gemm_kernel<1><<<dim3(192 / BN, MB), 256, GSMEM>>>(
            XW, Wph + op, Wpl + op, projb + layer * CC, X, 192, 192, shifted);
        ln_tok_kernel<<<TTOT / 8, 256>>>(X, XW, ln2g + layer * CC, ln2b + layer * CC);
        mma_gemm_kernel<2><<<dim3(768 / BN, MB), 256, GSMEM>>>(
            XW, W1h + o1, W1l + o1, fc1b + layer * HIDDIM, H1, 768, 192, 0);
        mma_gemm_kernel<3><<<dim3(192 / BN, MB), 256, GSMEM>>>(
            H1, W2h + o2, W2l + o2, fc2b + layer * CC, X, 192, 768, 0);
    }

    cudaMemcpyAsync(d_out, X, xbytes, cudaMemcpyDeviceToDevice);
}